// round 2
// baseline (speedup 1.0000x reference)
#include <cuda_runtime.h>
#include <cstdint>

#define NB 4913              // 17^3 triples
#define B_ 8
#define OHW 504
#define PLANE (OHW*OHW)      // 254016
#define NPIX (B_*PLANE)      // 2032128
#define CH 32

__device__ unsigned short g_triple[NPIX];
__device__ unsigned int   g_hist[NB];      // zero-initialized; re-zeroed by k_expand
__device__ __align__(16) float g_z1T[CH*NB];   // transposed: [o][t]
__device__ __align__(16) float g_lut[NB*CH];   // row-major:  [t][o] (128B rows)

// ---------------------------------------------------------------- packed 17-bin byte histogram
__device__ __forceinline__ void padd(unsigned h[5], unsigned b) {
    unsigned inc = 1u << ((b & 3u) * 8u);
    unsigned w = b >> 2;
    h[0] += (w == 0) ? inc : 0u;
    h[1] += (w == 1) ? inc : 0u;
    h[2] += (w == 2) ? inc : 0u;
    h[3] += (w == 3) ? inc : 0u;
    h[4] += (w == 4) ? inc : 0u;
}

// first-max argmax over 17 byte counters (ascending bins => lowest bin wins ties)
__device__ __forceinline__ int argmax17(const unsigned h[5]) {
    unsigned m = __vmaxu4(__vmaxu4(h[0], h[1]), __vmaxu4(h[2], h[3]));
    m = __vmaxu4(m, h[4]);
    m = __vmaxu4(m, m >> 16);
    m = __vmaxu4(m, m >> 8);
    unsigned M = (m & 0xFFu) * 0x01010101u;
    unsigned e;
    e = __vcmpeq4(h[0], M); if (e) return (int)((__ffs(e) - 1) >> 3);
    e = __vcmpeq4(h[1], M); if (e) return 4  + (int)((__ffs(e) - 1) >> 3);
    e = __vcmpeq4(h[2], M); if (e) return 8  + (int)((__ffs(e) - 1) >> 3);
    e = __vcmpeq4(h[3], M); if (e) return 12 + (int)((__ffs(e) - 1) >> 3);
    return 16;
}

#define TY 8
#define TX 126
#define TXP (TX + 10)   // 136

__global__ __launch_bounds__(256) void k_mode(const float* __restrict__ x) {
    __shared__ unsigned char  sbin[TY + 10][TXP];       // 2448 B
    __shared__ unsigned int   scol[5][TY][TXP];         // 21760 B
    __shared__ unsigned short strip[TY][TX];            // 2016 B
    __shared__ unsigned int   shist[NB];                // 19652 B

    int tid = threadIdx.x;
    int b   = blockIdx.z;
    int OY0 = blockIdx.y * TY;
    int OX0 = blockIdx.x * TX;

    for (int i = tid; i < NB; i += 256) shist[i] = 0u;

    const float* base = x + (size_t)b * 3 * 512 * 512;

    for (int c = 0; c < 3; c++) {
        __syncthreads();
        const float* plane = base + (size_t)c * 512 * 512;
        // ---- load + quantize (padding -> bin 0)
        for (int i = tid; i < (TY + 10) * TXP; i += 256) {
            int iy = i / TXP, jx = i - iy * TXP;
            int gy = OY0 - 1 + iy, gx = OX0 - 1 + jx;
            unsigned char bn = 0;
            if (gy >= 0 && gy < 512 && gx >= 0 && gx < 512) {
                float v = plane[gy * 512 + gx];
                int r = (int)rintf(__fmul_rn(v, 255.0f) * 0.0625f);  // round-half-even
                r = max(0, min(16, r));
                bn = (unsigned char)r;
            }
            sbin[iy][jx] = bn;
        }
        __syncthreads();
        // ---- column histograms via two-stacks: W[y] = P[y](rows y..7) + Q[y+10](rows 8..y+10)
        if (tid < TXP) {
            int jx = tid;
            unsigned P[8][5];
            unsigned h[5] = {0, 0, 0, 0, 0};
            #pragma unroll
            for (int y = 7; y >= 0; y--) {
                padd(h, (unsigned)sbin[y][jx]);
                #pragma unroll
                for (int w = 0; w < 5; w++) P[y][w] = h[w];
            }
            unsigned q[5] = {0, 0, 0, 0, 0};
            padd(q, (unsigned)sbin[8][jx]);
            padd(q, (unsigned)sbin[9][jx]);
            padd(q, (unsigned)sbin[10][jx]);
            #pragma unroll
            for (int y = 0; y < 8; y++) {
                if (y > 0) padd(q, (unsigned)sbin[y + 10][jx]);
                #pragma unroll
                for (int w = 0; w < 5; w++) scol[w][y][jx] = P[y][w] + q[w];
            }
        }
        __syncthreads();
        // ---- sliding window in x: 8 rows x 32 chunks of 4
        {
            int yy = tid >> 5;
            int x0 = (tid & 31) * 4;
            if (x0 < TX) {
                unsigned h[5] = {0, 0, 0, 0, 0};
                #pragma unroll
                for (int j = 0; j < 11; j++) {
                    #pragma unroll
                    for (int w = 0; w < 5; w++) h[w] += scol[w][yy][x0 + j];
                }
                int xe = min(x0 + 4, TX);
                for (int xx = x0; xx < xe; xx++) {
                    int bbin = argmax17(h);
                    if (c == 0)      strip[yy][xx] = (unsigned short)(bbin * 289);
                    else if (c == 1) strip[yy][xx] = (unsigned short)(strip[yy][xx] + bbin * 17);
                    else             strip[yy][xx] = (unsigned short)(strip[yy][xx] + bbin);
                    if (xx + 1 < xe) {
                        #pragma unroll
                        for (int w = 0; w < 5; w++)
                            h[w] += scol[w][yy][xx + 11] - scol[w][yy][xx];
                    }
                }
            }
        }
    }
    __syncthreads();
    size_t obase = ((size_t)b * OHW + OY0) * OHW + OX0;
    for (int i = tid; i < TY * TX; i += 256) {
        int yy = i / TX, xx = i - yy * TX;
        unsigned short t = strip[yy][xx];
        g_triple[obase + (size_t)yy * OHW + xx] = t;
        atomicAdd(&shist[t], 1u);
    }
    __syncthreads();
    for (int i = tid; i < NB; i += 256) {
        unsigned v = shist[i];
        if (v) atomicAdd(&g_hist[i], v);
    }
}

// ---------------------------------------------------------------- block reduce (2 doubles) + broadcast
__device__ __forceinline__ void reduce_bcast(double& s, double& s2, float* mean, float* rstd) {
    int tid = threadIdx.x, lane = tid & 31, wid = tid >> 5;
    #pragma unroll
    for (int off = 16; off; off >>= 1) {
        s  += __shfl_down_sync(0xFFFFFFFFu, s,  off);
        s2 += __shfl_down_sync(0xFFFFFFFFu, s2, off);
    }
    __shared__ double sh[8][2];
    __shared__ float  bc[2];
    if (lane == 0) { sh[wid][0] = s; sh[wid][1] = s2; }
    __syncthreads();
    if (tid == 0) {
        double ts = 0.0, tq = 0.0;
        #pragma unroll
        for (int w = 0; w < 8; w++) { ts += sh[w][0]; tq += sh[w][1]; }
        double mn = ts / (double)NPIX;
        double vr = tq / (double)NPIX - mn * mn;
        if (vr < 0.0) vr = 0.0;
        bc[0] = (float)mn;
        bc[1] = (float)(1.0 / sqrt(vr + 1e-5));
    }
    __syncthreads();
    *mean = bc[0]; *rstd = bc[1];
}

// ---------------------------------------------------------------- fused stage-1: BN stats + z1 (block o = channel o)
__global__ __launch_bounds__(256) void kA(const float* __restrict__ w1, const float* __restrict__ b1,
                                          const float* __restrict__ wd1, const float* __restrict__ bd1,
                                          const float* __restrict__ g1, const float* __restrict__ be1) {
    int o = blockIdx.x, tid = threadIdx.x;
    float wa = w1[o * 3], wb = w1[o * 3 + 1], wc = w1[o * 3 + 2];
    float bb = b1[o], wdv = wd1[o], bdv = bd1[o];
    float gg = g1[o], bee = be1[o];
    float ys[20];
    double s = 0.0, s2 = 0.0;
    #pragma unroll
    for (int i = 0; i < 20; i++) {
        int t = tid + i * 256;
        if (t < NB) {
            int m0 = t / 289; int rem = t - m0 * 289; int m1 = rem / 17; int m2 = rem - m1 * 17;
            float y = (wa * (float)m0 + wb * (float)m1 + wc * (float)m2) * 0.0625f + bb;
            y = y * wdv + bdv;
            ys[i] = y;
            double n = (double)g_hist[t];
            s  += n * (double)y;
            s2 += n * (double)y * (double)y;
        }
    }
    float mean, rstd;
    reduce_bcast(s, s2, &mean, &rstd);
    #pragma unroll
    for (int i = 0; i < 20; i++) {
        int t = tid + i * 256;
        if (t < NB) {
            float z = (ys[i] - mean) * rstd * gg + bee;
            z = (z >= 0.f) ? z : 0.01f * z;
            g_z1T[o * NB + t] = z;
        }
    }
}

// ---------------------------------------------------------------- fused stage-2: BN stats + final LUT
__global__ __launch_bounds__(256) void kB(const float* __restrict__ w2, const float* __restrict__ b2,
                                          const float* __restrict__ wd2, const float* __restrict__ bd2,
                                          const float* __restrict__ g2, const float* __restrict__ be2) {
    int o = blockIdx.x, tid = threadIdx.x;
    __shared__ float wsh[CH];
    if (tid < CH) wsh[tid] = w2[o * CH + tid];
    __syncthreads();
    float bb = b2[o], wdv = wd2[o], bdv = bd2[o];
    float gg = g2[o], bee = be2[o];
    float ys[20];
    double s = 0.0, s2 = 0.0;
    #pragma unroll
    for (int i = 0; i < 20; i++) {
        int t = tid + i * 256;
        if (t < NB) {
            float acc = 0.f;
            #pragma unroll
            for (int c = 0; c < CH; c++) acc += wsh[c] * g_z1T[c * NB + t];
            float y = (acc + bb) * wdv + bdv;
            ys[i] = y;
            double n = (double)g_hist[t];
            s  += n * (double)y;
            s2 += n * (double)y * (double)y;
        }
    }
    float mean, rstd;
    reduce_bcast(s, s2, &mean, &rstd);
    #pragma unroll
    for (int i = 0; i < 20; i++) {
        int t = tid + i * 256;
        if (t < NB) {
            float z = (ys[i] - mean) * rstd * gg + bee;
            z = (z >= 0.f) ? z : 0.01f * z;
            g_lut[t * CH + o] = z;
        }
    }
}

// ---------------------------------------------------------------- expand to [8,32,504,504] + re-zero hist
__global__ __launch_bounds__(256) void k_expand(float* __restrict__ out) {
    int tid = threadIdx.x;
    if (blockIdx.x < 20) {                     // re-zero g_hist for the next graph replay
        int i = blockIdx.x * 256 + tid;
        if (i < NB) g_hist[i] = 0u;
    }
    int p = blockIdx.x * 256 + tid;            // grid sized exactly to NPIX
    unsigned t = (unsigned)g_triple[p];
    const float4* row = reinterpret_cast<const float4*>(g_lut + (size_t)t * CH);
    float4 v[8];
    #pragma unroll
    for (int i = 0; i < 8; i++) v[i] = row[i];
    int b = p / PLANE;
    int r = p - b * PLANE;
    float* ob = out + (size_t)b * CH * PLANE + r;
    #pragma unroll
    for (int i = 0; i < 8; i++) {
        ob[(size_t)(4 * i + 0) * PLANE] = v[i].x;
        ob[(size_t)(4 * i + 1) * PLANE] = v[i].y;
        ob[(size_t)(4 * i + 2) * PLANE] = v[i].z;
        ob[(size_t)(4 * i + 3) * PLANE] = v[i].w;
    }
}

// ---------------------------------------------------------------- launch
extern "C" void kernel_launch(void* const* d_in, const int* in_sizes, int n_in,
                              void* d_out, int out_size) {
    const float* x   = (const float*)d_in[0];
    const float* w1  = (const float*)d_in[1];
    const float* b1  = (const float*)d_in[2];
    const float* wd1 = (const float*)d_in[3];
    const float* bd1 = (const float*)d_in[4];
    const float* g1  = (const float*)d_in[5];
    const float* be1 = (const float*)d_in[6];
    const float* w2  = (const float*)d_in[7];
    const float* b2  = (const float*)d_in[8];
    const float* bd2_= (const float*)d_in[10];
    const float* wd2 = (const float*)d_in[9];
    const float* g2  = (const float*)d_in[11];
    const float* be2 = (const float*)d_in[12];
    float* out = (float*)d_out;

    k_mode<<<dim3(OHW / TX, OHW / TY, B_), 256>>>(x);
    kA<<<CH, 256>>>(w1, b1, wd1, bd1, g1, be1);
    kB<<<CH, 256>>>(w2, b2, wd2, bd2_, g2, be2);
    k_expand<<<NPIX / 256, 256>>>(out);
}

// round 3
// speedup vs baseline: 1.2439x; 1.2439x over previous
#include <cuda_runtime.h>
#include <cstdint>

#define NB 4913              // 17^3 triples
#define B_ 8
#define OHW 504
#define PLANE (OHW*OHW)      // 254016 (divisible by 64)
#define NPIX (B_*PLANE)      // 2032128
#define CH 32

__device__ unsigned short g_triple[NPIX];
__device__ unsigned int   g_hist[NB];             // zero-init; re-zeroed by k_expand
__device__ __align__(16)  float g_z1T[CH*NB];     // transposed: [o][t]
__device__ __align__(128) float g_lut[NB*CH];     // row-major: [t][o], 128B rows

// ---------------------------------------------------------------- packed 17-bin byte histogram
__device__ __forceinline__ void padd(unsigned h[5], unsigned b) {
    unsigned inc = 1u << ((b & 3u) * 8u);
    unsigned w = b >> 2;
    h[0] += (w == 0) ? inc : 0u;
    h[1] += (w == 1) ? inc : 0u;
    h[2] += (w == 2) ? inc : 0u;
    h[3] += (w == 3) ? inc : 0u;
    h[4] += (w == 4) ? inc : 0u;
}

// first-max argmax over 17 byte counters (ascending bins => lowest bin wins ties)
__device__ __forceinline__ int argmax17(const unsigned h[5]) {
    unsigned m = __vmaxu4(__vmaxu4(h[0], h[1]), __vmaxu4(h[2], h[3]));
    m = __vmaxu4(m, h[4]);
    m = __vmaxu4(m, m >> 16);
    m = __vmaxu4(m, m >> 8);
    unsigned M = (m & 0xFFu) * 0x01010101u;
    unsigned e;
    e = __vcmpeq4(h[0], M); if (e) return (int)((__ffs(e) - 1) >> 3);
    e = __vcmpeq4(h[1], M); if (e) return 4  + (int)((__ffs(e) - 1) >> 3);
    e = __vcmpeq4(h[2], M); if (e) return 8  + (int)((__ffs(e) - 1) >> 3);
    e = __vcmpeq4(h[3], M); if (e) return 12 + (int)((__ffs(e) - 1) >> 3);
    return 16;
}

#define TY 8
#define TX 126
#define TXP (TX + 10)   // 136

__global__ __launch_bounds__(256) void k_mode(const float* __restrict__ x) {
    __shared__ unsigned char  sbin[TY + 10][TXP];       // 2448 B
    __shared__ unsigned int   scol[5][TY][TXP];         // 21760 B
    __shared__ unsigned short strip[TY][TX];            // 2016 B
    __shared__ unsigned int   shist[NB];                // 19652 B

    int tid = threadIdx.x;
    int b   = blockIdx.z;
    int OY0 = blockIdx.y * TY;
    int OX0 = blockIdx.x * TX;

    for (int i = tid; i < NB; i += 256) shist[i] = 0u;

    const float* base = x + (size_t)b * 3 * 512 * 512;

    for (int c = 0; c < 3; c++) {
        __syncthreads();
        const float* plane = base + (size_t)c * 512 * 512;
        // ---- load + quantize (padding -> bin 0)
        for (int i = tid; i < (TY + 10) * TXP; i += 256) {
            int iy = i / TXP, jx = i - iy * TXP;
            int gy = OY0 - 1 + iy, gx = OX0 - 1 + jx;
            unsigned char bn = 0;
            if (gy >= 0 && gy < 512 && gx >= 0 && gx < 512) {
                float v = plane[gy * 512 + gx];
                int r = (int)rintf(__fmul_rn(v, 255.0f) * 0.0625f);  // round-half-even
                r = max(0, min(16, r));
                bn = (unsigned char)r;
            }
            sbin[iy][jx] = bn;
        }
        __syncthreads();
        // ---- column histograms over 11 rows (distributed: full 256-thread occupancy)
        for (int i = tid; i < TY * TXP; i += 256) {
            int yy = i / TXP, jx = i - yy * TXP;
            unsigned h[5] = {0, 0, 0, 0, 0};
            #pragma unroll
            for (int r = 0; r < 11; r++) padd(h, (unsigned)sbin[yy + r][jx]);
            #pragma unroll
            for (int w = 0; w < 5; w++) scol[w][yy][jx] = h[w];
        }
        __syncthreads();
        // ---- sliding window in x: 8 rows x 32 chunks of 4
        {
            int yy = tid >> 5;
            int x0 = (tid & 31) * 4;
            if (x0 < TX) {
                unsigned h[5] = {0, 0, 0, 0, 0};
                #pragma unroll
                for (int j = 0; j < 11; j++) {
                    #pragma unroll
                    for (int w = 0; w < 5; w++) h[w] += scol[w][yy][x0 + j];
                }
                int xe = min(x0 + 4, TX);
                for (int xx = x0; xx < xe; xx++) {
                    int bbin = argmax17(h);
                    if (c == 0)      strip[yy][xx] = (unsigned short)(bbin * 289);
                    else if (c == 1) strip[yy][xx] = (unsigned short)(strip[yy][xx] + bbin * 17);
                    else             strip[yy][xx] = (unsigned short)(strip[yy][xx] + bbin);
                    if (xx + 1 < xe) {
                        #pragma unroll
                        for (int w = 0; w < 5; w++)
                            h[w] += scol[w][yy][xx + 11] - scol[w][yy][xx];
                    }
                }
            }
        }
    }
    __syncthreads();
    size_t obase = ((size_t)b * OHW + OY0) * OHW + OX0;
    for (int i = tid; i < TY * TX; i += 256) {
        int yy = i / TX, xx = i - yy * TX;
        unsigned short t = strip[yy][xx];
        g_triple[obase + (size_t)yy * OHW + xx] = t;
        atomicAdd(&shist[t], 1u);
    }
    __syncthreads();
    for (int i = tid; i < NB; i += 256) {
        unsigned v = shist[i];
        if (v) atomicAdd(&g_hist[i], v);
    }
}

// ---------------------------------------------------------------- block reduce (2 doubles) + broadcast
__device__ __forceinline__ void reduce_bcast(double& s, double& s2, float* mean, float* rstd) {
    int tid = threadIdx.x, lane = tid & 31, wid = tid >> 5;
    #pragma unroll
    for (int off = 16; off; off >>= 1) {
        s  += __shfl_down_sync(0xFFFFFFFFu, s,  off);
        s2 += __shfl_down_sync(0xFFFFFFFFu, s2, off);
    }
    __shared__ double sh[8][2];
    __shared__ float  bc[2];
    if (lane == 0) { sh[wid][0] = s; sh[wid][1] = s2; }
    __syncthreads();
    if (tid == 0) {
        double ts = 0.0, tq = 0.0;
        #pragma unroll
        for (int w = 0; w < 8; w++) { ts += sh[w][0]; tq += sh[w][1]; }
        double mn = ts / (double)NPIX;
        double vr = tq / (double)NPIX - mn * mn;
        if (vr < 0.0) vr = 0.0;
        bc[0] = (float)mn;
        bc[1] = (float)(1.0 / sqrt(vr + 1e-5));
    }
    __syncthreads();
    *mean = bc[0]; *rstd = bc[1];
}

// ---------------------------------------------------------------- fused stage-1: BN stats + z1 (block o = channel o)
__global__ __launch_bounds__(256) void kA(const float* __restrict__ w1, const float* __restrict__ b1,
                                          const float* __restrict__ wd1, const float* __restrict__ bd1,
                                          const float* __restrict__ g1, const float* __restrict__ be1) {
    int o = blockIdx.x, tid = threadIdx.x;
    float wa = w1[o * 3], wb = w1[o * 3 + 1], wc = w1[o * 3 + 2];
    float bb = b1[o], wdv = wd1[o], bdv = bd1[o];
    float gg = g1[o], bee = be1[o];
    float ys[20];
    double s = 0.0, s2 = 0.0;
    #pragma unroll
    for (int i = 0; i < 20; i++) {
        int t = tid + i * 256;
        if (t < NB) {
            int m0 = t / 289; int rem = t - m0 * 289; int m1 = rem / 17; int m2 = rem - m1 * 17;
            float y = (wa * (float)m0 + wb * (float)m1 + wc * (float)m2) * 0.0625f + bb;
            y = y * wdv + bdv;
            ys[i] = y;
            double n = (double)g_hist[t];
            s  += n * (double)y;
            s2 += n * (double)y * (double)y;
        }
    }
    float mean, rstd;
    reduce_bcast(s, s2, &mean, &rstd);
    #pragma unroll
    for (int i = 0; i < 20; i++) {
        int t = tid + i * 256;
        if (t < NB) {
            float z = (ys[i] - mean) * rstd * gg + bee;
            z = (z >= 0.f) ? z : 0.01f * z;
            g_z1T[o * NB + t] = z;
        }
    }
}

// ---------------------------------------------------------------- fused stage-2: BN stats + final LUT
__global__ __launch_bounds__(256) void kB(const float* __restrict__ w2, const float* __restrict__ b2,
                                          const float* __restrict__ wd2, const float* __restrict__ bd2,
                                          const float* __restrict__ g2, const float* __restrict__ be2) {
    int o = blockIdx.x, tid = threadIdx.x;
    __shared__ float wsh[CH];
    if (tid < CH) wsh[tid] = w2[o * CH + tid];
    __syncthreads();
    float bb = b2[o], wdv = wd2[o], bdv = bd2[o];
    float gg = g2[o], bee = be2[o];
    float ys[20];
    double s = 0.0, s2 = 0.0;
    #pragma unroll
    for (int i = 0; i < 20; i++) {
        int t = tid + i * 256;
        if (t < NB) {
            float acc = 0.f;
            #pragma unroll
            for (int c = 0; c < CH; c++) acc += wsh[c] * g_z1T[c * NB + t];
            float y = (acc + bb) * wdv + bdv;
            ys[i] = y;
            double n = (double)g_hist[t];
            s  += n * (double)y;
            s2 += n * (double)y * (double)y;
        }
    }
    float mean, rstd;
    reduce_bcast(s, s2, &mean, &rstd);
    #pragma unroll
    for (int i = 0; i < 20; i++) {
        int t = tid + i * 256;
        if (t < NB) {
            float z = (ys[i] - mean) * rstd * gg + bee;
            z = (z >= 0.f) ? z : 0.01f * z;
            g_lut[t * CH + o] = z;
        }
    }
}

// ---------------------------------------------------------------- expand to [8,32,504,504]
// Warp-cooperative row gather (4 lanes/pixel, rows are single 128B lines) +
// smem transpose (conflict-free, stride-66 rows) + coalesced STG.64 stores.
#define EXP_PX 64            // pixels per pass (PLANE % 64 == 0)
#define EXP_PASS 16          // passes per block => 1024 px/block
__global__ __launch_bounds__(256) void k_expand(float* __restrict__ out) {
    __shared__ float sm[CH][66];   // 8448 B
    int tid  = threadIdx.x;
    int w    = tid >> 5, lane = tid & 31;
    int b    = blockIdx.y;
    int r0   = blockIdx.x * (EXP_PX * EXP_PASS);

    // re-zero g_hist for the next graph replay (k_expand never reads it)
    if (b == 0 && blockIdx.x < 20) {
        int i = blockIdx.x * 256 + tid;
        if (i < NB) g_hist[i] = 0u;
    }

    const unsigned short* trip = g_triple + (size_t)b * PLANE;
    float* ob = out + (size_t)b * CH * PLANE;

    int c  = lane & 3;            // float4 chunk within row
    int pl = w * 8 + (lane >> 2); // pixel-local 0..63

    for (int pass = 0; pass < EXP_PASS; pass++) {
        int p0 = r0 + pass * EXP_PX;
        if (p0 >= PLANE) break;
        // ---- gather: warp covers 8 pixels, 2 LDG.128 each touching <=8 lines
        {
            unsigned t = (unsigned)trip[p0 + pl];
            const float4* row = reinterpret_cast<const float4*>(g_lut + (size_t)t * CH);
            float4 v0 = row[c];
            float4 v1 = row[c + 4];
            int ch0 = 4 * c;
            sm[ch0 + 0][pl]  = v0.x;
            sm[ch0 + 1][pl]  = v0.y;
            sm[ch0 + 2][pl]  = v0.z;
            sm[ch0 + 3][pl]  = v0.w;
            sm[ch0 + 16][pl] = v1.x;
            sm[ch0 + 17][pl] = v1.y;
            sm[ch0 + 18][pl] = v1.z;
            sm[ch0 + 19][pl] = v1.w;
        }
        __syncthreads();
        // ---- coalesced stores: warp w owns channels 4w..4w+3
        {
            #pragma unroll
            for (int k = 0; k < 4; k++) {
                int ch = w * 4 + k;
                float2 v = *reinterpret_cast<const float2*>(&sm[ch][lane * 2]);
                *reinterpret_cast<float2*>(&ob[(size_t)ch * PLANE + p0 + lane * 2]) = v;
            }
        }
        __syncthreads();
    }
}

// ---------------------------------------------------------------- launch
extern "C" void kernel_launch(void* const* d_in, const int* in_sizes, int n_in,
                              void* d_out, int out_size) {
    const float* x   = (const float*)d_in[0];
    const float* w1  = (const float*)d_in[1];
    const float* b1  = (const float*)d_in[2];
    const float* wd1 = (const float*)d_in[3];
    const float* bd1 = (const float*)d_in[4];
    const float* g1  = (const float*)d_in[5];
    const float* be1 = (const float*)d_in[6];
    const float* w2  = (const float*)d_in[7];
    const float* b2  = (const float*)d_in[8];
    const float* wd2 = (const float*)d_in[9];
    const float* bd2 = (const float*)d_in[10];
    const float* g2  = (const float*)d_in[11];
    const float* be2 = (const float*)d_in[12];
    float* out = (float*)d_out;

    k_mode<<<dim3(OHW / TX, OHW / TY, B_), 256>>>(x);
    kA<<<CH, 256>>>(w1, b1, wd1, bd1, g1, be1);
    kB<<<CH, 256>>>(w2, b2, wd2, bd2, g2, be2);
    int xblocks = (PLANE + EXP_PX * EXP_PASS - 1) / (EXP_PX * EXP_PASS);  // 249
    k_expand<<<dim3(xblocks, B_), 256>>>(out);
}

// round 4
// speedup vs baseline: 1.4453x; 1.1619x over previous
#include <cuda_runtime.h>
#include <cstdint>

#define NB 4913              // 17^3 triples
#define B_ 8
#define OHW 504
#define PLANE (OHW*OHW)      // 254016 (divisible by 64)
#define NPIX (B_*PLANE)      // 2032128
#define CH 32

__device__ unsigned short g_triple[NPIX];
__device__ unsigned int   g_hist[NB];             // zero-init; re-zeroed by k_expand
__device__ __align__(16)  float g_z1T[CH*NB];     // transposed: [o][t]
__device__ __align__(128) float g_lut[NB*CH];     // row-major: [t][o], 128B rows

// ---------------------------------------------------------------- packed 17-bin byte histogram
__device__ __forceinline__ void padd(unsigned h[5], unsigned b) {
    unsigned inc = 1u << ((b & 3u) * 8u);
    unsigned w = b >> 2;
    h[0] += (w == 0) ? inc : 0u;
    h[1] += (w == 1) ? inc : 0u;
    h[2] += (w == 2) ? inc : 0u;
    h[3] += (w == 3) ? inc : 0u;
    h[4] += (w == 4) ? inc : 0u;
}
__device__ __forceinline__ void psub(unsigned h[5], unsigned b) {
    unsigned inc = 1u << ((b & 3u) * 8u);
    unsigned w = b >> 2;
    h[0] -= (w == 0) ? inc : 0u;
    h[1] -= (w == 1) ? inc : 0u;
    h[2] -= (w == 2) ? inc : 0u;
    h[3] -= (w == 3) ? inc : 0u;
    h[4] -= (w == 4) ? inc : 0u;
}

// first-max argmax over 17 byte counters (ascending bins => lowest bin wins ties)
__device__ __forceinline__ int argmax17(const unsigned h[5]) {
    unsigned m = __vmaxu4(__vmaxu4(h[0], h[1]), __vmaxu4(h[2], h[3]));
    m = __vmaxu4(m, h[4]);
    m = __vmaxu4(m, m >> 16);
    m = __vmaxu4(m, m >> 8);
    unsigned M = (m & 0xFFu) * 0x01010101u;
    unsigned e;
    e = __vcmpeq4(h[0], M); if (e) return (int)((__ffs(e) - 1) >> 3);
    e = __vcmpeq4(h[1], M); if (e) return 4  + (int)((__ffs(e) - 1) >> 3);
    e = __vcmpeq4(h[2], M); if (e) return 8  + (int)((__ffs(e) - 1) >> 3);
    e = __vcmpeq4(h[3], M); if (e) return 12 + (int)((__ffs(e) - 1) >> 3);
    return 16;
}

#define TY 8
#define TX 118
#define TXP 128          // input columns per tile (128 halo-padded)
#define TXS 132          // swizzle-padded scol width: max px(127)=130

__device__ __forceinline__ int pxi(int x) { return x + (x >> 5); }   // bank-swizzle index

__global__ __launch_bounds__(256) void k_mode(const float* __restrict__ x) {
    __shared__ unsigned char  sbin[TY + 10][TXP];   // 2304 B
    __shared__ unsigned int   scol[5][TY][TXS];     // 21120 B, swizzled x-index
    __shared__ unsigned short strip[TY][TX];        // 1888 B
    __shared__ unsigned int   shist[NB];            // 19652 B

    int tid = threadIdx.x;
    int b   = blockIdx.z;
    int OY0 = blockIdx.y * TY;
    int OX0 = blockIdx.x * TX;
    int TXv = min(TX, OHW - OX0);                   // valid output cols this tile

    for (int i = tid; i < NB; i += 256) shist[i] = 0u;

    const float* base = x + (size_t)b * 3 * 512 * 512;

    for (int c = 0; c < 3; c++) {
        __syncthreads();
        const float* plane = base + (size_t)c * 512 * 512;
        // ---- load + quantize (padding / out-of-tile -> bin 0)
        for (int i = tid; i < (TY + 10) * TXP; i += 256) {
            int iy = i >> 7, jx = i & 127;
            int gy = OY0 - 1 + iy, gx = OX0 - 1 + jx;
            unsigned char bn = 0;
            if (gy >= 0 && gy < 512 && gx >= 0 && gx < 512) {
                float v = plane[gy * 512 + gx];
                int r = (int)rintf(__fmul_rn(v, 255.0f) * 0.0625f);  // round-half-even
                r = max(0, min(16, r));
                bn = (unsigned char)r;
            }
            sbin[iy][jx] = bn;
        }
        __syncthreads();
        // ---- column histograms, y-sliding: 128 columns x 2 half-strips = 256 tasks
        {
            int jx = tid & 127;
            int y0 = (tid >> 7) * 4;                 // 0 or 4
            int pj = pxi(jx);
            unsigned h[5] = {0, 0, 0, 0, 0};
            #pragma unroll
            for (int r = 0; r < 11; r++) padd(h, (unsigned)sbin[y0 + r][jx]);
            #pragma unroll
            for (int w = 0; w < 5; w++) scol[w][y0][pj] = h[w];
            #pragma unroll
            for (int k = 1; k < 4; k++) {
                padd(h, (unsigned)sbin[y0 + 10 + k][jx]);
                psub(h, (unsigned)sbin[y0 + k - 1][jx]);
                #pragma unroll
                for (int w = 0; w < 5; w++) scol[w][y0 + k][pj] = h[w];
            }
        }
        __syncthreads();
        // ---- sliding window in x: 8 rows x 32 chunks of 4 (swizzled, conflict-free)
        {
            int yy = tid >> 5;
            int x0 = (tid & 31) * 4;
            if (x0 < TXv) {
                unsigned h[5] = {0, 0, 0, 0, 0};
                #pragma unroll
                for (int j = 0; j < 11; j++) {
                    int p = pxi(x0 + j);
                    #pragma unroll
                    for (int w = 0; w < 5; w++) h[w] += scol[w][yy][p];
                }
                int xe = min(x0 + 4, TXv);
                for (int xx = x0; xx < xe; xx++) {
                    int bbin = argmax17(h);
                    if (c == 0)      strip[yy][xx] = (unsigned short)(bbin * 289);
                    else if (c == 1) strip[yy][xx] = (unsigned short)(strip[yy][xx] + bbin * 17);
                    else             strip[yy][xx] = (unsigned short)(strip[yy][xx] + bbin);
                    if (xx + 1 < xe) {
                        int pa = pxi(xx + 11), pb = pxi(xx);
                        #pragma unroll
                        for (int w = 0; w < 5; w++)
                            h[w] += scol[w][yy][pa] - scol[w][yy][pb];
                    }
                }
            }
        }
    }
    __syncthreads();
    size_t obase = ((size_t)b * OHW + OY0) * OHW + OX0;
    for (int i = tid; i < TY * TX; i += 256) {
        int yy = i / TX, xx = i - yy * TX;
        if (xx < TXv) {
            unsigned short t = strip[yy][xx];
            g_triple[obase + (size_t)yy * OHW + xx] = t;
            atomicAdd(&shist[t], 1u);
        }
    }
    __syncthreads();
    for (int i = tid; i < NB; i += 256) {
        unsigned v = shist[i];
        if (v) atomicAdd(&g_hist[i], v);
    }
}

// ---------------------------------------------------------------- block reduce (2 doubles) + broadcast
__device__ __forceinline__ void reduce_bcast(double& s, double& s2, float* mean, float* rstd) {
    int tid = threadIdx.x, lane = tid & 31, wid = tid >> 5;
    #pragma unroll
    for (int off = 16; off; off >>= 1) {
        s  += __shfl_down_sync(0xFFFFFFFFu, s,  off);
        s2 += __shfl_down_sync(0xFFFFFFFFu, s2, off);
    }
    __shared__ double sh[8][2];
    __shared__ float  bc[2];
    if (lane == 0) { sh[wid][0] = s; sh[wid][1] = s2; }
    __syncthreads();
    if (tid == 0) {
        double ts = 0.0, tq = 0.0;
        #pragma unroll
        for (int w = 0; w < 8; w++) { ts += sh[w][0]; tq += sh[w][1]; }
        double mn = ts / (double)NPIX;
        double vr = tq / (double)NPIX - mn * mn;
        if (vr < 0.0) vr = 0.0;
        bc[0] = (float)mn;
        bc[1] = (float)(1.0 / sqrt(vr + 1e-5));
    }
    __syncthreads();
    *mean = bc[0]; *rstd = bc[1];
}

// ---------------------------------------------------------------- fused stage-1: BN stats + z1 (block o = channel o)
__global__ __launch_bounds__(256) void kA(const float* __restrict__ w1, const float* __restrict__ b1,
                                          const float* __restrict__ wd1, const float* __restrict__ bd1,
                                          const float* __restrict__ g1, const float* __restrict__ be1) {
    int o = blockIdx.x, tid = threadIdx.x;
    float wa = w1[o * 3], wb = w1[o * 3 + 1], wc = w1[o * 3 + 2];
    float bb = b1[o], wdv = wd1[o], bdv = bd1[o];
    float gg = g1[o], bee = be1[o];
    float ys[20];
    double s = 0.0, s2 = 0.0;
    #pragma unroll
    for (int i = 0; i < 20; i++) {
        int t = tid + i * 256;
        if (t < NB) {
            int m0 = t / 289; int rem = t - m0 * 289; int m1 = rem / 17; int m2 = rem - m1 * 17;
            float y = (wa * (float)m0 + wb * (float)m1 + wc * (float)m2) * 0.0625f + bb;
            y = y * wdv + bdv;
            ys[i] = y;
            double n = (double)g_hist[t];
            s  += n * (double)y;
            s2 += n * (double)y * (double)y;
        }
    }
    float mean, rstd;
    reduce_bcast(s, s2, &mean, &rstd);
    #pragma unroll
    for (int i = 0; i < 20; i++) {
        int t = tid + i * 256;
        if (t < NB) {
            float z = (ys[i] - mean) * rstd * gg + bee;
            z = (z >= 0.f) ? z : 0.01f * z;
            g_z1T[o * NB + t] = z;
        }
    }
}

// ---------------------------------------------------------------- fused stage-2: BN stats + final LUT
__global__ __launch_bounds__(256) void kB(const float* __restrict__ w2, const float* __restrict__ b2,
                                          const float* __restrict__ wd2, const float* __restrict__ bd2,
                                          const float* __restrict__ g2, const float* __restrict__ be2) {
    int o = blockIdx.x, tid = threadIdx.x;
    __shared__ float wsh[CH];
    if (tid < CH) wsh[tid] = w2[o * CH + tid];
    __syncthreads();
    float bb = b2[o], wdv = wd2[o], bdv = bd2[o];
    float gg = g2[o], bee = be2[o];
    float ys[20];
    double s = 0.0, s2 = 0.0;
    #pragma unroll
    for (int i = 0; i < 20; i++) {
        int t = tid + i * 256;
        if (t < NB) {
            float acc = 0.f;
            #pragma unroll
            for (int c = 0; c < CH; c++) acc += wsh[c] * g_z1T[c * NB + t];
            float y = (acc + bb) * wdv + bdv;
            ys[i] = y;
            double n = (double)g_hist[t];
            s  += n * (double)y;
            s2 += n * (double)y * (double)y;
        }
    }
    float mean, rstd;
    reduce_bcast(s, s2, &mean, &rstd);
    #pragma unroll
    for (int i = 0; i < 20; i++) {
        int t = tid + i * 256;
        if (t < NB) {
            float z = (ys[i] - mean) * rstd * gg + bee;
            z = (z >= 0.f) ? z : 0.01f * z;
            g_lut[t * CH + o] = z;
        }
    }
}

// ---------------------------------------------------------------- expand to [8,32,504,504]
// Warp-cooperative row gather (4 lanes/pixel) + double-buffered smem transpose
// (one __syncthreads per pass) + coalesced float2 stores.
#define EXP_PX 64            // pixels per pass (PLANE % 64 == 0)
#define EXP_PASS 16          // passes per block => 1024 px/block
__global__ __launch_bounds__(256) void k_expand(float* __restrict__ out) {
    __shared__ float sm[2][CH][66];   // 16896 B
    int tid  = threadIdx.x;
    int w    = tid >> 5, lane = tid & 31;
    int b    = blockIdx.y;
    int r0   = blockIdx.x * (EXP_PX * EXP_PASS);

    // re-zero g_hist for the next graph replay (k_expand never reads it)
    if (b == 0 && blockIdx.x < 20) {
        int i = blockIdx.x * 256 + tid;
        if (i < NB) g_hist[i] = 0u;
    }

    const unsigned short* trip = g_triple + (size_t)b * PLANE;
    float* ob = out + (size_t)b * CH * PLANE;

    int c  = lane & 3;            // float4 chunk within row
    int pl = w * 8 + (lane >> 2); // pixel-local 0..63

    #pragma unroll 2
    for (int pass = 0; pass < EXP_PASS; pass++) {
        int p0 = r0 + pass * EXP_PX;
        if (p0 >= PLANE) break;
        int buf = pass & 1;
        // ---- gather: warp covers 8 pixels, 2 LDG.128 each touching <=8 lines
        {
            unsigned t = (unsigned)trip[p0 + pl];
            const float4* row = reinterpret_cast<const float4*>(g_lut + (size_t)t * CH);
            float4 v0 = row[c];
            float4 v1 = row[c + 4];
            int ch0 = 4 * c;
            sm[buf][ch0 + 0][pl]  = v0.x;
            sm[buf][ch0 + 1][pl]  = v0.y;
            sm[buf][ch0 + 2][pl]  = v0.z;
            sm[buf][ch0 + 3][pl]  = v0.w;
            sm[buf][ch0 + 16][pl] = v1.x;
            sm[buf][ch0 + 17][pl] = v1.y;
            sm[buf][ch0 + 18][pl] = v1.z;
            sm[buf][ch0 + 19][pl] = v1.w;
        }
        __syncthreads();
        // ---- coalesced stores: warp w owns channels 4w..4w+3
        {
            #pragma unroll
            for (int k = 0; k < 4; k++) {
                int ch = w * 4 + k;
                float2 v = *reinterpret_cast<const float2*>(&sm[buf][ch][lane * 2]);
                *reinterpret_cast<float2*>(&ob[(size_t)ch * PLANE + p0 + lane * 2]) = v;
            }
        }
    }
}

// ---------------------------------------------------------------- launch
extern "C" void kernel_launch(void* const* d_in, const int* in_sizes, int n_in,
                              void* d_out, int out_size) {
    const float* x   = (const float*)d_in[0];
    const float* w1  = (const float*)d_in[1];
    const float* b1  = (const float*)d_in[2];
    const float* wd1 = (const float*)d_in[3];
    const float* bd1 = (const float*)d_in[4];
    const float* g1  = (const float*)d_in[5];
    const float* be1 = (const float*)d_in[6];
    const float* w2  = (const float*)d_in[7];
    const float* b2  = (const float*)d_in[8];
    const float* wd2 = (const float*)d_in[9];
    const float* bd2 = (const float*)d_in[10];
    const float* g2  = (const float*)d_in[11];
    const float* be2 = (const float*)d_in[12];
    float* out = (float*)d_out;

    k_mode<<<dim3((OHW + TX - 1) / TX, OHW / TY, B_), 256>>>(x);   // (5,63,8)
    kA<<<CH, 256>>>(w1, b1, wd1, bd1, g1, be1);
    kB<<<CH, 256>>>(w2, b2, wd2, bd2, g2, be2);
    int xblocks = (PLANE + EXP_PX * EXP_PASS - 1) / (EXP_PX * EXP_PASS);  // 249
    k_expand<<<dim3(xblocks, B_), 256>>>(out);
}

// round 5
// speedup vs baseline: 1.5583x; 1.0782x over previous
#include <cuda_runtime.h>
#include <cstdint>

#define NB 4913              // 17^3 triples
#define NH 2457              // packed u16 hist words (2 triples/word)
#define B_ 8
#define OHW 504
#define PLANE (OHW*OHW)      // 254016 (divisible by 64)
#define NPIX (B_*PLANE)      // 2032128
#define CH 32

__device__ unsigned short g_triple[NPIX];
__device__ unsigned int   g_hist[NB];             // zero-init; re-zeroed by k_expand
__device__ __align__(16)  float g_z1T[CH*NB];     // transposed: [o][t]
__device__ __align__(128) float g_lut[NB*CH];     // row-major: [t][o], 128B rows

// ---------------------------------------------------------------- packed 17-bin byte histogram
__device__ __forceinline__ void padd(unsigned h[5], unsigned b) {
    unsigned inc = 1u << ((b & 3u) * 8u);
    unsigned w = b >> 2;
    h[0] += (w == 0) ? inc : 0u;
    h[1] += (w == 1) ? inc : 0u;
    h[2] += (w == 2) ? inc : 0u;
    h[3] += (w == 3) ? inc : 0u;
    h[4] += (w == 4) ? inc : 0u;
}
__device__ __forceinline__ void psub(unsigned h[5], unsigned b) {
    unsigned inc = 1u << ((b & 3u) * 8u);
    unsigned w = b >> 2;
    h[0] -= (w == 0) ? inc : 0u;
    h[1] -= (w == 1) ? inc : 0u;
    h[2] -= (w == 2) ? inc : 0u;
    h[3] -= (w == 3) ? inc : 0u;
    h[4] -= (w == 4) ? inc : 0u;
}

// first-max argmax over 17 byte counters (ascending bins => lowest bin wins ties)
__device__ __forceinline__ int argmax17(const unsigned h[5]) {
    unsigned m = __vmaxu4(__vmaxu4(h[0], h[1]), __vmaxu4(h[2], h[3]));
    m = __vmaxu4(m, h[4]);
    m = __vmaxu4(m, m >> 16);
    m = __vmaxu4(m, m >> 8);
    unsigned M = (m & 0xFFu) * 0x01010101u;
    unsigned e;
    e = __vcmpeq4(h[0], M); if (e) return (int)((__ffs(e) - 1) >> 3);
    e = __vcmpeq4(h[1], M); if (e) return 4  + (int)((__ffs(e) - 1) >> 3);
    e = __vcmpeq4(h[2], M); if (e) return 8  + (int)((__ffs(e) - 1) >> 3);
    e = __vcmpeq4(h[3], M); if (e) return 12 + (int)((__ffs(e) - 1) >> 3);
    return 16;
}

#define TY 8
#define TX 118
#define TXP 128          // input columns per tile (halo-padded)
#define TXS 132          // swizzle-padded scol width

__device__ __forceinline__ int pxi(int x) { return x + (x >> 5); }   // bank-swizzle index

__global__ __launch_bounds__(256) void k_mode(const float* __restrict__ x) {
    __shared__ unsigned char  sbin[TY + 10][TXP];   // 2304 B
    __shared__ unsigned int   scol[5][TY][TXS];     // 21120 B, swizzled x-index
    __shared__ unsigned int   shist[NH];            // 9828 B (u16-packed)

    int tid = threadIdx.x;
    int b   = blockIdx.z;
    int OY0 = blockIdx.y * TY;
    int OX0 = blockIdx.x * TX;
    int TXv = min(TX, OHW - OX0);                   // valid output cols this tile

    for (int i = tid; i < NH; i += 256) shist[i] = 0u;

    const float* base = x + (size_t)b * 3 * 512 * 512;

    int yy = tid >> 5;
    int x0 = (tid & 31) * 4;
    unsigned tl[4] = {0, 0, 0, 0};                  // register triple accumulators

    for (int c = 0; c < 3; c++) {
        const float* plane = base + (size_t)c * 512 * 512;
        // ---- load + quantize (padding / out-of-tile -> bin 0)
        #pragma unroll
        for (int k = 0; k < 9; k++) {
            int i = tid + k * 256;
            int iy = i >> 7, jx = i & 127;
            int gy = OY0 - 1 + iy, gx = OX0 - 1 + jx;
            unsigned char bn = 0;
            if (gy >= 0 && gy < 512 && gx >= 0 && gx < 512) {
                float v = plane[gy * 512 + gx];
                int r = (int)rintf(__fmul_rn(v, 255.0f) * 0.0625f);  // round-half-even
                r = max(0, min(16, r));
                bn = (unsigned char)r;
            }
            sbin[iy][jx] = bn;
        }
        __syncthreads();
        // ---- column histograms, y-sliding: 128 columns x 2 half-strips = 256 tasks
        {
            int jx = tid & 127;
            int y0 = (tid >> 7) * 4;                 // 0 or 4
            int pj = pxi(jx);
            unsigned h[5] = {0, 0, 0, 0, 0};
            #pragma unroll
            for (int r = 0; r < 11; r++) padd(h, (unsigned)sbin[y0 + r][jx]);
            #pragma unroll
            for (int w = 0; w < 5; w++) scol[w][y0][pj] = h[w];
            #pragma unroll
            for (int k = 1; k < 4; k++) {
                padd(h, (unsigned)sbin[y0 + 10 + k][jx]);
                psub(h, (unsigned)sbin[y0 + k - 1][jx]);
                #pragma unroll
                for (int w = 0; w < 5; w++) scol[w][y0 + k][pj] = h[w];
            }
        }
        __syncthreads();
        // ---- sliding window in x: 8 rows x 32 chunks of 4 (swizzled, conflict-free)
        if (x0 < TXv) {
            unsigned h[5] = {0, 0, 0, 0, 0};
            #pragma unroll
            for (int j = 0; j < 11; j++) {
                int p = pxi(x0 + j);
                #pragma unroll
                for (int w = 0; w < 5; w++) h[w] += scol[w][yy][p];
            }
            unsigned mul = (c == 0) ? 289u : (c == 1) ? 17u : 1u;
            int xe = min(x0 + 4, TXv);
            #pragma unroll
            for (int k = 0; k < 4; k++) {
                int xx = x0 + k;
                if (xx < xe) {
                    tl[k] += (unsigned)argmax17(h) * mul;
                    if (xx + 1 < xe) {
                        int pa = pxi(xx + 11), pb = pxi(xx);
                        #pragma unroll
                        for (int w = 0; w < 5; w++)
                            h[w] += scol[w][yy][pa] - scol[w][yy][pb];
                    }
                }
            }
        }
        // no trailing barrier needed: next load writes sbin (all reads done pre-sync),
        // next column writes scol only after its own barrier.
        __syncthreads();
    }
    // ---- write triples (packed u32 pairs, indices always even) + local hist
    if (x0 < TXv) {
        int xe = min(x0 + 4, TXv);                   // 2 or 4 (TXv even)
        size_t orow = ((size_t)b * OHW + OY0 + yy) * OHW + OX0 + x0;
        unsigned int* op = reinterpret_cast<unsigned int*>(&g_triple[orow]);
        op[0] = tl[0] | (tl[1] << 16);
        atomicAdd(&shist[tl[0] >> 1], 1u << ((tl[0] & 1u) * 16u));
        atomicAdd(&shist[tl[1] >> 1], 1u << ((tl[1] & 1u) * 16u));
        if (xe == x0 + 4) {
            op[1] = tl[2] | (tl[3] << 16);
            atomicAdd(&shist[tl[2] >> 1], 1u << ((tl[2] & 1u) * 16u));
            atomicAdd(&shist[tl[3] >> 1], 1u << ((tl[3] & 1u) * 16u));
        }
    }
    __syncthreads();
    for (int i = tid; i < NH; i += 256) {
        unsigned wv = shist[i];
        unsigned lo = wv & 0xFFFFu, hi = wv >> 16;
        if (lo) atomicAdd(&g_hist[2 * i], lo);
        if (hi) atomicAdd(&g_hist[2 * i + 1], hi);   // t=4913 slot never occurs
    }
}

// ---------------------------------------------------------------- block reduce (2 doubles) + broadcast
__device__ __forceinline__ void reduce_bcast(double& s, double& s2, float* mean, float* rstd) {
    int tid = threadIdx.x, lane = tid & 31, wid = tid >> 5;
    #pragma unroll
    for (int off = 16; off; off >>= 1) {
        s  += __shfl_down_sync(0xFFFFFFFFu, s,  off);
        s2 += __shfl_down_sync(0xFFFFFFFFu, s2, off);
    }
    __shared__ double sh[8][2];
    __shared__ float  bc[2];
    if (lane == 0) { sh[wid][0] = s; sh[wid][1] = s2; }
    __syncthreads();
    if (tid == 0) {
        double ts = 0.0, tq = 0.0;
        #pragma unroll
        for (int w = 0; w < 8; w++) { ts += sh[w][0]; tq += sh[w][1]; }
        double mn = ts / (double)NPIX;
        double vr = tq / (double)NPIX - mn * mn;
        if (vr < 0.0) vr = 0.0;
        bc[0] = (float)mn;
        bc[1] = (float)(1.0 / sqrt(vr + 1e-5));
    }
    __syncthreads();
    *mean = bc[0]; *rstd = bc[1];
}

// ---------------------------------------------------------------- fused stage-1: BN stats + z1 (block o = channel o)
__global__ __launch_bounds__(256) void kA(const float* __restrict__ w1, const float* __restrict__ b1,
                                          const float* __restrict__ wd1, const float* __restrict__ bd1,
                                          const float* __restrict__ g1, const float* __restrict__ be1) {
    int o = blockIdx.x, tid = threadIdx.x;
    float wa = w1[o * 3], wb = w1[o * 3 + 1], wc = w1[o * 3 + 2];
    float bb = b1[o], wdv = wd1[o], bdv = bd1[o];
    float gg = g1[o], bee = be1[o];
    float ys[20];
    double s = 0.0, s2 = 0.0;
    #pragma unroll
    for (int i = 0; i < 20; i++) {
        int t = tid + i * 256;
        if (t < NB) {
            int m0 = t / 289; int rem = t - m0 * 289; int m1 = rem / 17; int m2 = rem - m1 * 17;
            float y = (wa * (float)m0 + wb * (float)m1 + wc * (float)m2) * 0.0625f + bb;
            y = y * wdv + bdv;
            ys[i] = y;
            double n = (double)g_hist[t];
            s  += n * (double)y;
            s2 += n * (double)y * (double)y;
        }
    }
    float mean, rstd;
    reduce_bcast(s, s2, &mean, &rstd);
    #pragma unroll
    for (int i = 0; i < 20; i++) {
        int t = tid + i * 256;
        if (t < NB) {
            float z = (ys[i] - mean) * rstd * gg + bee;
            z = (z >= 0.f) ? z : 0.01f * z;
            g_z1T[o * NB + t] = z;
        }
    }
}

// ---------------------------------------------------------------- fused stage-2: BN stats + final LUT
__global__ __launch_bounds__(256) void kB(const float* __restrict__ w2, const float* __restrict__ b2,
                                          const float* __restrict__ wd2, const float* __restrict__ bd2,
                                          const float* __restrict__ g2, const float* __restrict__ be2) {
    int o = blockIdx.x, tid = threadIdx.x;
    __shared__ float wsh[CH];
    if (tid < CH) wsh[tid] = w2[o * CH + tid];
    __syncthreads();
    float bb = b2[o], wdv = wd2[o], bdv = bd2[o];
    float gg = g2[o], bee = be2[o];
    float ys[20];
    double s = 0.0, s2 = 0.0;
    #pragma unroll
    for (int i = 0; i < 20; i++) {
        int t = tid + i * 256;
        if (t < NB) {
            float acc = 0.f;
            #pragma unroll
            for (int c = 0; c < CH; c++) acc += wsh[c] * g_z1T[c * NB + t];
            float y = (acc + bb) * wdv + bdv;
            ys[i] = y;
            double n = (double)g_hist[t];
            s  += n * (double)y;
            s2 += n * (double)y * (double)y;
        }
    }
    float mean, rstd;
    reduce_bcast(s, s2, &mean, &rstd);
    #pragma unroll
    for (int i = 0; i < 20; i++) {
        int t = tid + i * 256;
        if (t < NB) {
            float z = (ys[i] - mean) * rstd * gg + bee;
            z = (z >= 0.f) ? z : 0.01f * z;
            g_lut[t * CH + o] = z;
        }
    }
}

// ---------------------------------------------------------------- expand to [8,32,504,504]
// Warp-cooperative gather + SOFTWARE-PIPELINED prefetch: next pass's triple+LUT
// loads issue before the barrier, hiding L2 latency under the store phase.
#define EXP_PX 64            // pixels per pass (PLANE % 64 == 0)
#define EXP_PASS 16          // passes per block => 1024 px/block
__global__ __launch_bounds__(256) void k_expand(float* __restrict__ out) {
    __shared__ float sm[2][CH][66];   // 16896 B
    int tid  = threadIdx.x;
    int w    = tid >> 5, lane = tid & 31;
    int b    = blockIdx.y;
    int r0   = blockIdx.x * (EXP_PX * EXP_PASS);

    // re-zero g_hist for the next graph replay (k_expand never reads it)
    if (b == 0 && blockIdx.x < 20) {
        int i = blockIdx.x * 256 + tid;
        if (i < NB) g_hist[i] = 0u;
    }

    const unsigned short* trip = g_triple + (size_t)b * PLANE;
    float* ob = out + (size_t)b * CH * PLANE;

    int c  = lane & 3;            // float4 chunk within row
    int pl = w * 8 + (lane >> 2); // pixel-local 0..63
    int npass = min(EXP_PASS, (PLANE - r0) / EXP_PX);

    // prologue prefetch
    unsigned t0 = (unsigned)trip[r0 + pl];
    const float4* row = reinterpret_cast<const float4*>(g_lut + (size_t)t0 * CH);
    float4 v0 = row[c];
    float4 v1 = row[c + 4];

    for (int pass = 0; pass < npass; pass++) {
        int p0  = r0 + pass * EXP_PX;
        int buf = pass & 1;
        int ch0 = 4 * c;
        sm[buf][ch0 + 0][pl]  = v0.x;
        sm[buf][ch0 + 1][pl]  = v0.y;
        sm[buf][ch0 + 2][pl]  = v0.z;
        sm[buf][ch0 + 3][pl]  = v0.w;
        sm[buf][ch0 + 16][pl] = v1.x;
        sm[buf][ch0 + 17][pl] = v1.y;
        sm[buf][ch0 + 18][pl] = v1.z;
        sm[buf][ch0 + 19][pl] = v1.w;
        // prefetch next pass before the barrier (overlaps with store phase)
        if (pass + 1 < npass) {
            unsigned tn = (unsigned)trip[p0 + EXP_PX + pl];
            const float4* rn = reinterpret_cast<const float4*>(g_lut + (size_t)tn * CH);
            v0 = rn[c];
            v1 = rn[c + 4];
        }
        __syncthreads();
        #pragma unroll
        for (int k = 0; k < 4; k++) {
            int ch = w * 4 + k;
            float2 v = *reinterpret_cast<const float2*>(&sm[buf][ch][lane * 2]);
            *reinterpret_cast<float2*>(&ob[(size_t)ch * PLANE + p0 + lane * 2]) = v;
        }
    }
}

// ---------------------------------------------------------------- launch
extern "C" void kernel_launch(void* const* d_in, const int* in_sizes, int n_in,
                              void* d_out, int out_size) {
    const float* x   = (const float*)d_in[0];
    const float* w1  = (const float*)d_in[1];
    const float* b1  = (const float*)d_in[2];
    const float* wd1 = (const float*)d_in[3];
    const float* bd1 = (const float*)d_in[4];
    const float* g1  = (const float*)d_in[5];
    const float* be1 = (const float*)d_in[6];
    const float* w2  = (const float*)d_in[7];
    const float* b2  = (const float*)d_in[8];
    const float* wd2 = (const float*)d_in[9];
    const float* bd2 = (const float*)d_in[10];
    const float* g2  = (const float*)d_in[11];
    const float* be2 = (const float*)d_in[12];
    float* out = (float*)d_out;

    k_mode<<<dim3((OHW + TX - 1) / TX, OHW / TY, B_), 256>>>(x);   // (5,63,8)
    kA<<<CH, 256>>>(w1, b1, wd1, bd1, g1, be1);
    kB<<<CH, 256>>>(w2, b2, wd2, bd2, g2, be2);
    int xblocks = (PLANE + EXP_PX * EXP_PASS - 1) / (EXP_PX * EXP_PASS);  // 249
    k_expand<<<dim3(xblocks, B_), 256>>>(out);
}